// round 2
// baseline (speedup 1.0000x reference)
#include <cuda_runtime.h>
#include <math.h>

#define BT   32          // B*T
#define LSEQ 512
#define DIM  512
#define NH   8
#define ED   64
#define NTOT 1536        // packed Q|K|V width

// Packed projected tensor: [bt][l][ Q(512) | K(512) | V(512) ]
__device__ float g_qkv[(size_t)BT * LSEQ * NTOT];

// ---------------------------------------------------------------------------
// Projection GEMM: for each bt, C[l][n] = sum_d X[l][d] * W[d][n]
// n-tile selects which input/weight (Q/K/V). 128x128x16 tile, 8x8 micro-tile.
// ---------------------------------------------------------------------------
__global__ __launch_bounds__(256, 2) void proj_kernel(
    const float* __restrict__ q_in, const float* __restrict__ k_in,
    const float* __restrict__ v_in,
    const float* __restrict__ wq, const float* __restrict__ wk,
    const float* __restrict__ wv)
{
    __shared__ float As[16][132];   // [k][m], padded: 16B-aligned rows, low STS conflicts
    __shared__ float Bs[16][128];   // [k][n]

    const int bt    = blockIdx.z;
    const int ntile = blockIdx.x;          // 0..11
    const int sel   = ntile >> 2;          // 0=Q,1=K,2=V
    const int n0    = ntile * 128;
    const int wn0   = n0 - sel * 512;      // column within selected weight
    const int m0    = blockIdx.y * 128;

    const float* X = (sel == 0 ? q_in : (sel == 1 ? k_in : v_in))
                     + (size_t)bt * LSEQ * DIM;
    const float* W = (sel == 0 ? wq : (sel == 1 ? wk : wv));
    float* C = g_qkv + (size_t)bt * LSEQ * NTOT;

    const int tid = threadIdx.x;
    const int r0  = (tid >> 4) * 8;        // micro-tile row base
    const int c0  = (tid & 15) * 8;        // micro-tile col base

    float acc[8][8];
#pragma unroll
    for (int i = 0; i < 8; i++)
#pragma unroll
        for (int j = 0; j < 8; j++) acc[i][j] = 0.f;

    for (int k0 = 0; k0 < DIM; k0 += 16) {
        __syncthreads();
        // Load A tile 128x16 (transposed into As[k][m])
#pragma unroll
        for (int i = 0; i < 2; i++) {
            int idx = tid + i * 256;       // 0..511
            int row = idx >> 2;            // 0..127
            int kk  = (idx & 3) * 4;       // 0,4,8,12
            float4 v = *(const float4*)&X[(size_t)(m0 + row) * DIM + k0 + kk];
            As[kk + 0][row] = v.x;
            As[kk + 1][row] = v.y;
            As[kk + 2][row] = v.z;
            As[kk + 3][row] = v.w;
        }
        // Load B tile 16x128
#pragma unroll
        for (int i = 0; i < 2; i++) {
            int idx = tid + i * 256;       // 0..511
            int kr  = idx >> 5;            // 0..15
            int nn  = (idx & 31) * 4;      // 0..124
            *(float4*)&Bs[kr][nn] =
                *(const float4*)&W[(size_t)(k0 + kr) * 512 + wn0 + nn];
        }
        __syncthreads();

#pragma unroll
        for (int k = 0; k < 16; k++) {
            float a[8], b[8];
            *(float4*)&a[0] = *(const float4*)&As[k][r0];
            *(float4*)&a[4] = *(const float4*)&As[k][r0 + 4];
            *(float4*)&b[0] = *(const float4*)&Bs[k][c0];
            *(float4*)&b[4] = *(const float4*)&Bs[k][c0 + 4];
#pragma unroll
            for (int i = 0; i < 8; i++)
#pragma unroll
                for (int j = 0; j < 8; j++)
                    acc[i][j] = fmaf(a[i], b[j], acc[i][j]);
        }
    }

#pragma unroll
    for (int i = 0; i < 8; i++) {
        float* crow = C + (size_t)(m0 + r0 + i) * NTOT + n0 + c0;
        float4 v0 = make_float4(acc[i][0], acc[i][1], acc[i][2], acc[i][3]);
        float4 v1 = make_float4(acc[i][4], acc[i][5], acc[i][6], acc[i][7]);
        *(float4*)&crow[0] = v0;
        *(float4*)&crow[4] = v1;
    }
}

// ---------------------------------------------------------------------------
// Flash-style attention: one block per (bt, h, 128-query tile).
// Thread t owns query row l0+t entirely: Q row + O accumulator in registers,
// online softmax with K/V/mask tiles (32 keys) staged in shared memory.
// Final: out += (w_head[h]/lsum) * O  via atomicAdd (out pre-zeroed).
// ---------------------------------------------------------------------------
__global__ __launch_bounds__(128) void attn_kernel(
    const float* __restrict__ mask, const float* __restrict__ w_head,
    const float* __restrict__ tau, const float* __restrict__ delta,
    float* __restrict__ out)
{
    __shared__ float Ks[32][64];
    __shared__ float Vs[32][64];
    __shared__ float Ms[128][33];   // [l][s], pad 33 -> conflict-free scalar reads

    const int bt  = blockIdx.z;
    const int h   = blockIdx.y;
    const int l0  = blockIdx.x * 128;
    const int tid = threadIdx.x;
    const int l   = l0 + tid;

    const float* base = g_qkv + (size_t)bt * LSEQ * NTOT;

    // Q row into registers
    float q[64];
    {
        const float* qp = base + (size_t)l * NTOT + h * ED;
#pragma unroll
        for (int e = 0; e < 64; e += 4) {
            float4 v = *(const float4*)&qp[e];
            q[e] = v.x; q[e + 1] = v.y; q[e + 2] = v.z; q[e + 3] = v.w;
        }
    }
    const float tv = tau[0];
    const float dv = delta[0];

    float o[64];
#pragma unroll
    for (int e = 0; e < 64; e++) o[e] = 0.f;
    float m = -1e30f, lsum = 0.f;

    for (int s0 = 0; s0 < LSEQ; s0 += 32) {
        __syncthreads();
        // K/V tiles (32 keys x 64)
#pragma unroll
        for (int i = 0; i < 4; i++) {
            int idx = tid + i * 128;       // 0..511
            int s   = idx >> 4;            // 0..31
            int e4  = (idx & 15) * 4;
            const float* row = base + (size_t)(s0 + s) * NTOT + h * ED;
            *(float4*)&Ks[s][e4] = *(const float4*)&row[512 + e4];
            *(float4*)&Vs[s][e4] = *(const float4*)&row[1024 + e4];
        }
        // mask tile [128 l][32 s] (coalesced load along s)
#pragma unroll
        for (int i = 0; i < 8; i++) {
            int idx = tid + i * 128;       // 0..1023
            int ml  = idx >> 3;            // 0..127
            int s4  = (idx & 7) * 4;       // 0..28
            float4 mv = *(const float4*)&mask[(size_t)(l0 + ml) * LSEQ + s0 + s4];
            Ms[ml][s4 + 0] = mv.x;
            Ms[ml][s4 + 1] = mv.y;
            Ms[ml][s4 + 2] = mv.z;
            Ms[ml][s4 + 3] = mv.w;
        }
        __syncthreads();

        // scores for this key tile
        float sc[32];
#pragma unroll
        for (int s = 0; s < 32; s++) {
            float acc = 0.f;
#pragma unroll
            for (int e = 0; e < 64; e += 4) {
                float4 kv = *(const float4*)&Ks[s][e];
                acc = fmaf(q[e], kv.x, acc);
                acc = fmaf(q[e + 1], kv.y, acc);
                acc = fmaf(q[e + 2], kv.z, acc);
                acc = fmaf(q[e + 3], kv.w, acc);
            }
            sc[s] = (acc * tv + dv) * 0.125f * Ms[tid][s];
        }

        // online softmax update
        float tmax = sc[0];
#pragma unroll
        for (int s = 1; s < 32; s++) tmax = fmaxf(tmax, sc[s]);
        float m_new = fmaxf(m, tmax);
        float corr  = __expf(m - m_new);
        lsum *= corr;
#pragma unroll
        for (int e = 0; e < 64; e++) o[e] *= corr;
        m = m_new;

#pragma unroll
        for (int s = 0; s < 32; s++) {
            float p = __expf(sc[s] - m);
            lsum += p;
#pragma unroll
            for (int e = 0; e < 64; e += 4) {
                float4 vv = *(const float4*)&Vs[s][e];
                o[e]     = fmaf(p, vv.x, o[e]);
                o[e + 1] = fmaf(p, vv.y, o[e + 1]);
                o[e + 2] = fmaf(p, vv.z, o[e + 2]);
                o[e + 3] = fmaf(p, vv.w, o[e + 3]);
            }
        }
    }

    const float wfac = w_head[h] / lsum;
    float* op = out + ((size_t)bt * LSEQ + l) * ED;
#pragma unroll
    for (int e = 0; e < 64; e++) atomicAdd(&op[e], o[e] * wfac);
}

// ---------------------------------------------------------------------------
extern "C" void kernel_launch(void* const* d_in, const int* in_sizes, int n_in,
                              void* d_out, int out_size) {
    (void)in_sizes; (void)n_in;
    const float* queries = (const float*)d_in[0];
    const float* keys    = (const float*)d_in[1];
    const float* values  = (const float*)d_in[2];
    const float* amask   = (const float*)d_in[3];
    const float* Wq      = (const float*)d_in[4];
    const float* Wk      = (const float*)d_in[5];
    const float* Wv      = (const float*)d_in[6];
    const float* w_head  = (const float*)d_in[7];
    const float* tau     = (const float*)d_in[8];
    const float* delta   = (const float*)d_in[9];
    float* out = (float*)d_out;

    cudaMemsetAsync(out, 0, (size_t)out_size * sizeof(float));

    dim3 pg(12, 4, BT);          // n-tiles x m-tiles x bt
    proj_kernel<<<pg, 256>>>(queries, keys, values, Wq, Wk, Wv);

    dim3 ag(4, NH, BT);          // l-tiles x heads x bt
    attn_kernel<<<ag, 128>>>(amask, w_head, tau, delta, out);
}

// round 3
// speedup vs baseline: 1.0683x; 1.0683x over previous
#include <cuda_runtime.h>
#include <math.h>

#define BT   32          // B*T
#define LSEQ 512
#define DIM  512
#define NH   8
#define ED   64
#define NTOT 1536        // packed Q|K|V width

// Packed projected tensor: [bt][l][ Q(512) | K(512) | V(512) ]
__device__ float g_qkv[(size_t)BT * LSEQ * NTOT];

// ---------------------------------------------------------------------------
// Projection GEMM: for each bt, C[l][n] = sum_d X[l][d] * W[d][n]
// n-tile selects which input/weight (Q/K/V). 128x128x16 tile, 8x8 micro-tile.
// ---------------------------------------------------------------------------
__global__ __launch_bounds__(256, 2) void proj_kernel(
    const float* __restrict__ q_in, const float* __restrict__ k_in,
    const float* __restrict__ v_in,
    const float* __restrict__ wq, const float* __restrict__ wk,
    const float* __restrict__ wv)
{
    __shared__ float As[16][132];
    __shared__ float Bs[16][128];

    const int bt    = blockIdx.z;
    const int ntile = blockIdx.x;          // 0..11
    const int sel   = ntile >> 2;          // 0=Q,1=K,2=V
    const int n0    = ntile * 128;
    const int wn0   = n0 - sel * 512;
    const int m0    = blockIdx.y * 128;

    const float* X = (sel == 0 ? q_in : (sel == 1 ? k_in : v_in))
                     + (size_t)bt * LSEQ * DIM;
    const float* W = (sel == 0 ? wq : (sel == 1 ? wk : wv));
    float* C = g_qkv + (size_t)bt * LSEQ * NTOT;

    const int tid = threadIdx.x;
    const int r0  = (tid >> 4) * 8;
    const int c0  = (tid & 15) * 8;

    float acc[8][8];
#pragma unroll
    for (int i = 0; i < 8; i++)
#pragma unroll
        for (int j = 0; j < 8; j++) acc[i][j] = 0.f;

    for (int k0 = 0; k0 < DIM; k0 += 16) {
        __syncthreads();
#pragma unroll
        for (int i = 0; i < 2; i++) {
            int idx = tid + i * 256;
            int row = idx >> 2;
            int kk  = (idx & 3) * 4;
            float4 v = *(const float4*)&X[(size_t)(m0 + row) * DIM + k0 + kk];
            As[kk + 0][row] = v.x;
            As[kk + 1][row] = v.y;
            As[kk + 2][row] = v.z;
            As[kk + 3][row] = v.w;
        }
#pragma unroll
        for (int i = 0; i < 2; i++) {
            int idx = tid + i * 256;
            int kr  = idx >> 5;
            int nn  = (idx & 31) * 4;
            *(float4*)&Bs[kr][nn] =
                *(const float4*)&W[(size_t)(k0 + kr) * 512 + wn0 + nn];
        }
        __syncthreads();

#pragma unroll
        for (int k = 0; k < 16; k++) {
            float a[8], b[8];
            *(float4*)&a[0] = *(const float4*)&As[k][r0];
            *(float4*)&a[4] = *(const float4*)&As[k][r0 + 4];
            *(float4*)&b[0] = *(const float4*)&Bs[k][c0];
            *(float4*)&b[4] = *(const float4*)&Bs[k][c0 + 4];
#pragma unroll
            for (int i = 0; i < 8; i++)
#pragma unroll
                for (int j = 0; j < 8; j++)
                    acc[i][j] = fmaf(a[i], b[j], acc[i][j]);
        }
    }

#pragma unroll
    for (int i = 0; i < 8; i++) {
        float* crow = C + (size_t)(m0 + r0 + i) * NTOT + n0 + c0;
        float4 v0 = make_float4(acc[i][0], acc[i][1], acc[i][2], acc[i][3]);
        float4 v1 = make_float4(acc[i][4], acc[i][5], acc[i][6], acc[i][7]);
        *(float4*)&crow[0] = v0;
        *(float4*)&crow[4] = v1;
    }
}

// ---------------------------------------------------------------------------
// Attention v2: register-tiled GEMMs. One block per (bt, h, 64-query tile).
// 128 threads as 16x8 (ry, cx). Thread query rows: {ry+16i, i=0..3}.
//   S-GEMM: thread computes S[ry+16i][cx+8j] (4x4 micro-tile).
//   softmax: threads 0..63 each own one query row (online max/sum).
//   PV-GEMM: thread accumulates O[ry+16i][cx*8 .. cx*8+7] (4x8 micro-tile).
// Final: out += (w_head[h]/lsum) * O via atomicAdd (out pre-zeroed).
// ---------------------------------------------------------------------------
__global__ __launch_bounds__(128) void attn_kernel(
    const float* __restrict__ mask, const float* __restrict__ w_head,
    const float* __restrict__ tau, const float* __restrict__ delta,
    float* __restrict__ out)
{
    __shared__ float Qs[64][68];
    __shared__ float Ks[32][68];
    __shared__ float Vs[32][68];
    __shared__ float Ss[64][36];
    __shared__ float rowc[64];
    __shared__ float rowf[64];

    const int bt  = blockIdx.z;
    const int h   = blockIdx.y;
    const int l0  = blockIdx.x * 64;
    const int tid = threadIdx.x;
    const int ry  = tid >> 3;     // 0..15
    const int cx  = tid & 7;      // 0..7

    const float* base = g_qkv + (size_t)bt * LSEQ * NTOT;

    // Q tile 64x64 -> shared
#pragma unroll
    for (int i = 0; i < 8; i++) {
        int idx = tid + i * 128;
        int r   = idx >> 4;
        int e4  = (idx & 15) << 2;
        *(float4*)&Qs[r][e4] =
            *(const float4*)&base[(size_t)(l0 + r) * NTOT + h * ED + e4];
    }

    const float tv = tau[0] * 0.125f;
    const float dv = delta[0] * 0.125f;

    float o[4][8];
#pragma unroll
    for (int i = 0; i < 4; i++)
#pragma unroll
        for (int j = 0; j < 8; j++) o[i][j] = 0.f;
    float m = -1e30f, lsum = 0.f;   // meaningful on tid<64 only

    for (int s0 = 0; s0 < LSEQ; s0 += 32) {
        __syncthreads();
        // K/V tiles (32 keys x 64e)
#pragma unroll
        for (int i = 0; i < 4; i++) {
            int idx = tid + i * 128;
            int r   = idx >> 4;
            int e4  = (idx & 15) << 2;
            const float* row = base + (size_t)(s0 + r) * NTOT + h * ED;
            *(float4*)&Ks[r][e4] = *(const float4*)&row[512 + e4];
            *(float4*)&Vs[r][e4] = *(const float4*)&row[1024 + e4];
        }
        __syncthreads();

        // ---- S = Q K^T (64x32x64) ----
        float s[4][4];
#pragma unroll
        for (int i = 0; i < 4; i++)
#pragma unroll
            for (int j = 0; j < 4; j++) s[i][j] = 0.f;

#pragma unroll
        for (int e4 = 0; e4 < 16; e4++) {
            float4 qv[4], kv[4];
#pragma unroll
            for (int i = 0; i < 4; i++)
                qv[i] = *(const float4*)&Qs[ry + 16 * i][e4 * 4];
#pragma unroll
            for (int j = 0; j < 4; j++)
                kv[j] = *(const float4*)&Ks[cx + 8 * j][e4 * 4];
#pragma unroll
            for (int i = 0; i < 4; i++)
#pragma unroll
                for (int j = 0; j < 4; j++) {
                    s[i][j] = fmaf(qv[i].x, kv[j].x, s[i][j]);
                    s[i][j] = fmaf(qv[i].y, kv[j].y, s[i][j]);
                    s[i][j] = fmaf(qv[i].z, kv[j].z, s[i][j]);
                    s[i][j] = fmaf(qv[i].w, kv[j].w, s[i][j]);
                }
        }
#pragma unroll
        for (int i = 0; i < 4; i++)
#pragma unroll
            for (int j = 0; j < 4; j++)
                Ss[ry + 16 * i][cx + 8 * j] = s[i][j];
        __syncthreads();

        // ---- softmax: thread t owns query row t ----
        if (tid < 64) {
            const float* mrow = mask + (size_t)(l0 + tid) * LSEQ + s0;
            float sc[32];
            float tmax = -1e30f;
#pragma unroll
            for (int k4 = 0; k4 < 8; k4++) {
                float4 sv = *(const float4*)&Ss[tid][k4 * 4];
                float4 mv = *(const float4*)&mrow[k4 * 4];
                float a0 = fmaf(sv.x, tv, dv) * mv.x;
                float a1 = fmaf(sv.y, tv, dv) * mv.y;
                float a2 = fmaf(sv.z, tv, dv) * mv.z;
                float a3 = fmaf(sv.w, tv, dv) * mv.w;
                sc[k4 * 4 + 0] = a0; sc[k4 * 4 + 1] = a1;
                sc[k4 * 4 + 2] = a2; sc[k4 * 4 + 3] = a3;
                tmax = fmaxf(tmax, fmaxf(fmaxf(a0, a1), fmaxf(a2, a3)));
            }
            float m_new = fmaxf(m, tmax);
            float c  = __expf(m - m_new);
            float ls = lsum * c;
#pragma unroll
            for (int k4 = 0; k4 < 8; k4++) {
                float p0 = __expf(sc[k4 * 4 + 0] - m_new);
                float p1 = __expf(sc[k4 * 4 + 1] - m_new);
                float p2 = __expf(sc[k4 * 4 + 2] - m_new);
                float p3 = __expf(sc[k4 * 4 + 3] - m_new);
                ls += (p0 + p1) + (p2 + p3);
                *(float4*)&Ss[tid][k4 * 4] = make_float4(p0, p1, p2, p3);
            }
            lsum = ls;
            m = m_new;
            rowc[tid] = c;
        }
        __syncthreads();

        // ---- rescale O, then O += P V (64x64x32) ----
        float cc[4];
#pragma unroll
        for (int i = 0; i < 4; i++) cc[i] = rowc[ry + 16 * i];
#pragma unroll
        for (int i = 0; i < 4; i++)
#pragma unroll
            for (int j = 0; j < 8; j++) o[i][j] *= cc[i];

#pragma unroll
        for (int k4 = 0; k4 < 8; k4++) {
            float pk[4][4];
#pragma unroll
            for (int i = 0; i < 4; i++)
                *(float4*)&pk[i][0] = *(const float4*)&Ss[ry + 16 * i][k4 * 4];
#pragma unroll
            for (int kk = 0; kk < 4; kk++) {
                float4 va = *(const float4*)&Vs[k4 * 4 + kk][cx * 8];
                float4 vb = *(const float4*)&Vs[k4 * 4 + kk][cx * 8 + 4];
#pragma unroll
                for (int i = 0; i < 4; i++) {
                    float p = pk[i][kk];
                    o[i][0] = fmaf(p, va.x, o[i][0]);
                    o[i][1] = fmaf(p, va.y, o[i][1]);
                    o[i][2] = fmaf(p, va.z, o[i][2]);
                    o[i][3] = fmaf(p, va.w, o[i][3]);
                    o[i][4] = fmaf(p, vb.x, o[i][4]);
                    o[i][5] = fmaf(p, vb.y, o[i][5]);
                    o[i][6] = fmaf(p, vb.z, o[i][6]);
                    o[i][7] = fmaf(p, vb.w, o[i][7]);
                }
            }
        }
    }

    if (tid < 64) rowf[tid] = w_head[h] / lsum;
    __syncthreads();

#pragma unroll
    for (int i = 0; i < 4; i++) {
        float f = rowf[ry + 16 * i];
        float* op = out + ((size_t)bt * LSEQ + l0 + ry + 16 * i) * ED + cx * 8;
#pragma unroll
        for (int j = 0; j < 8; j++) atomicAdd(&op[j], o[i][j] * f);
    }
}

// ---------------------------------------------------------------------------
extern "C" void kernel_launch(void* const* d_in, const int* in_sizes, int n_in,
                              void* d_out, int out_size) {
    (void)in_sizes; (void)n_in;
    const float* queries = (const float*)d_in[0];
    const float* keys    = (const float*)d_in[1];
    const float* values  = (const float*)d_in[2];
    const float* amask   = (const float*)d_in[3];
    const float* Wq      = (const float*)d_in[4];
    const float* Wk      = (const float*)d_in[5];
    const float* Wv      = (const float*)d_in[6];
    const float* w_head  = (const float*)d_in[7];
    const float* tau     = (const float*)d_in[8];
    const float* delta   = (const float*)d_in[9];
    float* out = (float*)d_out;

    cudaMemsetAsync(out, 0, (size_t)out_size * sizeof(float));

    dim3 pg(12, 4, BT);          // n-tiles x m-tiles x bt
    proj_kernel<<<pg, 256>>>(queries, keys, values, Wq, Wk, Wv);

    dim3 ag(8, NH, BT);          // 64-query tiles x heads x bt
    attn_kernel<<<ag, 128>>>(amask, w_head, tau, delta, out);
}

// round 9
// speedup vs baseline: 1.4188x; 1.3280x over previous
#include <cuda_runtime.h>
#include <cuda_bf16.h>
#include <math.h>
#include <cstdint>

#define BT   32          // B*T
#define LSEQ 512
#define DIM  512
#define NH   8
#define ED   64
#define NTOT 1536        // packed Q|K|V width

// Packed projected tensor: [bt][l][ Q(512) | K(512) | V(512) ]
__device__ float g_qkv[(size_t)BT * LSEQ * NTOT];

// Split-bf16 operands (prepared once per launch)
__device__ __nv_bfloat16 g_xhi[(size_t)3 * BT * LSEQ * DIM];   // [sel][bt][l][k]
__device__ __nv_bfloat16 g_xlo[(size_t)3 * BT * LSEQ * DIM];
__device__ __nv_bfloat16 g_whi[(size_t)3 * DIM * DIM];         // [sel][n][k]  (transposed)
__device__ __nv_bfloat16 g_wlo[(size_t)3 * DIM * DIM];

// ===========================================================================
// Warp-MMA helpers (baseline PTX: sm_80-class, safe at compute_103)
// ===========================================================================
__device__ __forceinline__ uint32_t smem_to_u32(const void* p) {
    uint32_t a;
    asm("{ .reg .u64 t; cvta.to.shared.u64 t, %1; cvt.u32.u64 %0, t; }"
        : "=r"(a) : "l"(p));
    return a;
}

__device__ __forceinline__ void ldsm_x4(uint32_t r[4], uint32_t addr) {
    asm volatile("ldmatrix.sync.aligned.m8n8.x4.shared.b16 {%0,%1,%2,%3}, [%4];"
                 : "=r"(r[0]), "=r"(r[1]), "=r"(r[2]), "=r"(r[3]) : "r"(addr));
}

__device__ __forceinline__ void mma16816(float c[4], const uint32_t a[4],
                                         const uint32_t b[2]) {
    asm volatile(
        "mma.sync.aligned.m16n8k16.row.col.f32.bf16.bf16.f32 "
        "{%0,%1,%2,%3}, {%4,%5,%6,%7}, {%8,%9}, {%0,%1,%2,%3};"
        : "+f"(c[0]), "+f"(c[1]), "+f"(c[2]), "+f"(c[3])
        : "r"(a[0]), "r"(a[1]), "r"(a[2]), "r"(a[3]), "r"(b[0]), "r"(b[1]));
}

// ===========================================================================
// Prep kernels: split fp32 -> (bf16 hi, bf16 lo)
// ===========================================================================
__global__ __launch_bounds__(256) void prep_x(
    const float* __restrict__ q, const float* __restrict__ k,
    const float* __restrict__ v)
{
    const int sel = blockIdx.y;
    const float* s = (sel == 0 ? q : (sel == 1 ? k : v));
    size_t i = ((size_t)blockIdx.x * 256 + threadIdx.x) * 4;
    float4 x = *(const float4*)&s[i];
    size_t o = (size_t)sel * BT * LSEQ * DIM + i;
    float xs[4] = {x.x, x.y, x.z, x.w};
#pragma unroll
    for (int j = 0; j < 4; j++) {
        __nv_bfloat16 h = __float2bfloat16(xs[j]);
        float lo = xs[j] - __bfloat162float(h);
        g_xhi[o + j] = h;
        g_xlo[o + j] = __float2bfloat16(lo);
    }
}

__global__ __launch_bounds__(256) void prep_w(
    const float* __restrict__ wq, const float* __restrict__ wk,
    const float* __restrict__ wv)
{
    const int sel = blockIdx.y;
    const float* w = (sel == 0 ? wq : (sel == 1 ? wk : wv));
    int idx = blockIdx.x * 256 + threadIdx.x;     // over 512*512
    int kk = idx >> 9;
    int n  = idx & 511;                           // coalesced read along n
    float x = w[(size_t)kk * 512 + n];
    __nv_bfloat16 h = __float2bfloat16(x);
    float lo = x - __bfloat162float(h);
    size_t o = (size_t)sel * DIM * DIM + (size_t)n * DIM + kk;  // [n][k]
    g_whi[o] = h;
    g_wlo[o] = __float2bfloat16(lo);
}

// ===========================================================================
// Projection via warp MMA (HMMA): C[128x128] per block, 8 warps, 64x32 warp
// tiles. K chunks of 64 bf16 in smem (stride 72 bf16 = 144B, ldmatrix
// conflict-free). Split-bf16 3-term accumulate in fp32 fragments.
// ===========================================================================
#define SM_AHI 0
#define SM_ALO 18432
#define SM_BHI 36864
#define SM_BLO 55296
#define SM_TOT 73728
#define ROWB   144          // 72 bf16 row stride in bytes

__global__ __launch_bounds__(256, 2) void proj_mma_kernel()
{
    extern __shared__ __align__(128) char smem[];
    const uint32_t sb = smem_to_u32(smem);
    const int tid  = threadIdx.x;
    const int wid  = tid >> 5;
    const int lane = tid & 31;

    const int bt    = blockIdx.z;
    const int ntile = blockIdx.x;          // 0..11
    const int sel   = ntile >> 2;          // 0=Q,1=K,2=V
    const int n0    = ntile << 7;
    const int wn0   = n0 - (sel << 9);     // row within [n][k] weight
    const int m0    = blockIdx.y << 7;

    const __nv_bfloat16* xhi = g_xhi + ((size_t)sel * BT + bt) * LSEQ * DIM;
    const __nv_bfloat16* xlo = g_xlo + ((size_t)sel * BT + bt) * LSEQ * DIM;
    const __nv_bfloat16* whi = g_whi + (size_t)sel * DIM * DIM;
    const __nv_bfloat16* wlo = g_wlo + (size_t)sel * DIM * DIM;

    const int wm = (wid >> 2) * 64;        // warp row base: 0 or 64
    const int wn = (wid & 3) * 32;         // warp col base: 0..96

    // ldmatrix per-lane offsets (bytes)
    // A (x4 = one m16k16 frag): lanes 0-15 -> rows 0-15 @k0; 16-31 -> rows @k+8
    const uint32_t a_off = (uint32_t)((lane & 15) * ROWB + (lane >> 4) * 16);
    // B (x4 = two n-octet frags): l/8=0: oct0 klo, 1: oct0 khi, 2: oct1 klo, 3: oct1 khi
    const uint32_t b_off = (uint32_t)((((lane >> 4) & 1) * 8 + (lane & 7)) * ROWB
                                      + ((lane >> 3) & 1) * 16);

    float c[4][4][4];                      // [mi][ni][frag]
#pragma unroll
    for (int mi = 0; mi < 4; mi++)
#pragma unroll
        for (int ni = 0; ni < 4; ni++)
#pragma unroll
            for (int j = 0; j < 4; j++) c[mi][ni][j] = 0.f;

    for (int ki = 0; ki < 8; ki++) {
        const int k0 = ki * 64;
        __syncthreads();
        // Stage A/B hi+lo: 128 rows x 64 bf16 each
#pragma unroll
        for (int i = 0; i < 4; i++) {
            int idx = tid + i * 256;       // 0..1023
            int row = idx >> 3;
            int c8  = idx & 7;             // 8-bf16 (16B) chunk
            uint32_t so = (uint32_t)(row * ROWB + c8 * 16);
            size_t xo = (size_t)(m0 + row) * DIM + k0 + c8 * 8;
            size_t wo = (size_t)(wn0 + row) * DIM + k0 + c8 * 8;
            *(uint4*)(smem + SM_AHI + so) = *(const uint4*)(xhi + xo);
            *(uint4*)(smem + SM_ALO + so) = *(const uint4*)(xlo + xo);
            *(uint4*)(smem + SM_BHI + so) = *(const uint4*)(whi + wo);
            *(uint4*)(smem + SM_BLO + so) = *(const uint4*)(wlo + wo);
        }
        __syncthreads();

#pragma unroll
        for (int ks = 0; ks < 4; ks++) {   // 4 x k16 within the 64 chunk
            uint32_t bhi[4][2], blo[4][2];
#pragma unroll
            for (int nj = 0; nj < 2; nj++) {
                uint32_t bd = sb + (uint32_t)((wn + nj * 16) * ROWB + ks * 32) + b_off;
                uint32_t t[4];
                ldsm_x4(t, bd + SM_BHI);
                bhi[nj * 2][0] = t[0]; bhi[nj * 2][1] = t[1];
                bhi[nj * 2 + 1][0] = t[2]; bhi[nj * 2 + 1][1] = t[3];
                ldsm_x4(t, bd + SM_BLO);
                blo[nj * 2][0] = t[0]; blo[nj * 2][1] = t[1];
                blo[nj * 2 + 1][0] = t[2]; blo[nj * 2 + 1][1] = t[3];
            }
#pragma unroll
            for (int mi = 0; mi < 4; mi++) {
                uint32_t ahi[4], alo[4];
                uint32_t ad = sb + (uint32_t)((wm + mi * 16) * ROWB + ks * 32) + a_off;
                ldsm_x4(ahi, ad + SM_AHI);
                ldsm_x4(alo, ad + SM_ALO);
#pragma unroll
                for (int ni = 0; ni < 4; ni++) {
                    mma16816(c[mi][ni], ahi, bhi[ni]);
                    mma16816(c[mi][ni], ahi, blo[ni]);
                    mma16816(c[mi][ni], alo, bhi[ni]);
                }
            }
        }
    }

    // Writeout: frag (g=lane/4, tg=lane%4) -> rows g, g+8; cols 2*tg, +1
    const int g  = lane >> 2;
    const int tg = (lane & 3) * 2;
    float* Cb = g_qkv + ((size_t)bt * LSEQ + m0) * NTOT + n0;
#pragma unroll
    for (int mi = 0; mi < 4; mi++)
#pragma unroll
        for (int ni = 0; ni < 4; ni++) {
            int r   = wm + mi * 16 + g;
            int col = wn + ni * 8 + tg;
            *(float2*)&Cb[(size_t)r * NTOT + col] =
                make_float2(c[mi][ni][0], c[mi][ni][1]);
            *(float2*)&Cb[(size_t)(r + 8) * NTOT + col] =
                make_float2(c[mi][ni][2], c[mi][ni][3]);
        }
}

// ---------------------------------------------------------------------------
// Attention v2 (unchanged, known good): register-tiled fp32 GEMMs.
// ---------------------------------------------------------------------------
__global__ __launch_bounds__(128) void attn_kernel(
    const float* __restrict__ mask, const float* __restrict__ w_head,
    const float* __restrict__ tau, const float* __restrict__ delta,
    float* __restrict__ out)
{
    __shared__ float Qs[64][68];
    __shared__ float Ks[32][68];
    __shared__ float Vs[32][68];
    __shared__ float Ss[64][36];
    __shared__ float rowc[64];
    __shared__ float rowf[64];

    const int bt  = blockIdx.z;
    const int h   = blockIdx.y;
    const int l0  = blockIdx.x * 64;
    const int tid = threadIdx.x;
    const int ry  = tid >> 3;
    const int cx  = tid & 7;

    const float* base = g_qkv + (size_t)bt * LSEQ * NTOT;

#pragma unroll
    for (int i = 0; i < 8; i++) {
        int idx = tid + i * 128;
        int r   = idx >> 4;
        int e4  = (idx & 15) << 2;
        *(float4*)&Qs[r][e4] =
            *(const float4*)&base[(size_t)(l0 + r) * NTOT + h * ED + e4];
    }

    const float tv = tau[0] * 0.125f;
    const float dv = delta[0] * 0.125f;

    float o[4][8];
#pragma unroll
    for (int i = 0; i < 4; i++)
#pragma unroll
        for (int j = 0; j < 8; j++) o[i][j] = 0.f;
    float m = -1e30f, lsum = 0.f;

    for (int s0 = 0; s0 < LSEQ; s0 += 32) {
        __syncthreads();
#pragma unroll
        for (int i = 0; i < 4; i++) {
            int idx = tid + i * 128;
            int r   = idx >> 4;
            int e4  = (idx & 15) << 2;
            const float* row = base + (size_t)(s0 + r) * NTOT + h * ED;
            *(float4*)&Ks[r][e4] = *(const float4*)&row[512 + e4];
            *(float4*)&Vs[r][e4] = *(const float4*)&row[1024 + e4];
        }
        __syncthreads();

        float s[4][4];
#pragma unroll
        for (int i = 0; i < 4; i++)
#pragma unroll
            for (int j = 0; j < 4; j++) s[i][j] = 0.f;

#pragma unroll
        for (int e4 = 0; e4 < 16; e4++) {
            float4 qv[4], kv[4];
#pragma unroll
            for (int i = 0; i < 4; i++)
                qv[i] = *(const float4*)&Qs[ry + 16 * i][e4 * 4];
#pragma unroll
            for (int j = 0; j < 4; j++)
                kv[j] = *(const float4*)&Ks[cx + 8 * j][e4 * 4];
#pragma unroll
            for (int i = 0; i < 4; i++)
#pragma unroll
                for (int j = 0; j < 4; j++) {
                    s[i][j] = fmaf(qv[i].x, kv[j].x, s[i][j]);
                    s[i][j] = fmaf(qv[i].y, kv[j].y, s[i][j]);
                    s[i][j] = fmaf(qv[i].z, kv[j].z, s[i][j]);
                    s[i][j] = fmaf(qv[i].w, kv[j].w, s[i][j]);
                }
        }
#pragma unroll
        for (int i = 0; i < 4; i++)
#pragma unroll
            for (int j = 0; j < 4; j++)
                Ss[ry + 16 * i][cx + 8 * j] = s[i][j];
        __syncthreads();

        if (tid < 64) {
            const float* mrow = mask + (size_t)(l0 + tid) * LSEQ + s0;
            float sc[32];
            float tmax = -1e30f;
#pragma unroll
            for (int k4 = 0; k4 < 8; k4++) {
                float4 sv = *(const float4*)&Ss[tid][k4 * 4];
                float4 mv = *(const float4*)&mrow[k4 * 4];
                float a0 = fmaf(sv.x, tv, dv) * mv.x;
                float a1 = fmaf(sv.y, tv, dv) * mv.y;
                float a2 = fmaf(sv.z, tv, dv) * mv.z;
                float a3 = fmaf(sv.w, tv, dv) * mv.w;
                sc[k4 * 4 + 0] = a0; sc[k4 * 4 + 1] = a1;
                sc[k4 * 4 + 2] = a2; sc[k4 * 4 + 3] = a3;
                tmax = fmaxf(tmax, fmaxf(fmaxf(a0, a1), fmaxf(a2, a3)));
            }
            float m_new = fmaxf(m, tmax);
            float cr = __expf(m - m_new);
            float ls = lsum * cr;
#pragma unroll
            for (int k4 = 0; k4 < 8; k4++) {
                float p0 = __expf(sc[k4 * 4 + 0] - m_new);
                float p1 = __expf(sc[k4 * 4 + 1] - m_new);
                float p2 = __expf(sc[k4 * 4 + 2] - m_new);
                float p3 = __expf(sc[k4 * 4 + 3] - m_new);
                ls += (p0 + p1) + (p2 + p3);
                *(float4*)&Ss[tid][k4 * 4] = make_float4(p0, p1, p2, p3);
            }
            lsum = ls;
            m = m_new;
            rowc[tid] = cr;
        }
        __syncthreads();

        float cc[4];
#pragma unroll
        for (int i = 0; i < 4; i++) cc[i] = rowc[ry + 16 * i];
#pragma unroll
        for (int i = 0; i < 4; i++)
#pragma unroll
            for (int j = 0; j < 8; j++) o[i][j] *= cc[i];

#pragma unroll
        for (int k4 = 0; k4 < 8; k4++) {
            float pk[4][4];
#pragma unroll
            for (int i = 0; i < 4; i++)
                *(float4*)&pk[i][0] = *(const float4*)&Ss[ry + 16 * i][k4 * 4];
#pragma unroll
            for (int kk = 0; kk < 4; kk++) {
                float4 va = *(const float4*)&Vs[k4 * 4 + kk][cx * 8];
                float4 vb = *(const float4*)&Vs[k4 * 4 + kk][cx * 8 + 4];
#pragma unroll
                for (int i = 0; i < 4; i++) {
                    float p = pk[i][kk];
                    o[i][0] = fmaf(p, va.x, o[i][0]);
                    o[i][1] = fmaf(p, va.y, o[i][1]);
                    o[i][2] = fmaf(p, va.z, o[i][2]);
                    o[i][3] = fmaf(p, va.w, o[i][3]);
                    o[i][4] = fmaf(p, vb.x, o[i][4]);
                    o[i][5] = fmaf(p, vb.y, o[i][5]);
                    o[i][6] = fmaf(p, vb.z, o[i][6]);
                    o[i][7] = fmaf(p, vb.w, o[i][7]);
                }
            }
        }
    }

    if (tid < 64) rowf[tid] = w_head[h] / lsum;
    __syncthreads();

#pragma unroll
    for (int i = 0; i < 4; i++) {
        float f = rowf[ry + 16 * i];
        float* op = out + ((size_t)bt * LSEQ + l0 + ry + 16 * i) * ED + cx * 8;
#pragma unroll
        for (int j = 0; j < 8; j++) atomicAdd(&op[j], o[i][j] * f);
    }
}

// ---------------------------------------------------------------------------
extern "C" void kernel_launch(void* const* d_in, const int* in_sizes, int n_in,
                              void* d_out, int out_size) {
    (void)in_sizes; (void)n_in;
    const float* queries = (const float*)d_in[0];
    const float* keys    = (const float*)d_in[1];
    const float* values  = (const float*)d_in[2];
    const float* amask   = (const float*)d_in[3];
    const float* Wq      = (const float*)d_in[4];
    const float* Wk      = (const float*)d_in[5];
    const float* Wv      = (const float*)d_in[6];
    const float* w_head  = (const float*)d_in[7];
    const float* tau     = (const float*)d_in[8];
    const float* delta   = (const float*)d_in[9];
    float* out = (float*)d_out;

    cudaFuncSetAttribute(proj_mma_kernel,
                         cudaFuncAttributeMaxDynamicSharedMemorySize, SM_TOT);

    cudaMemsetAsync(out, 0, (size_t)out_size * sizeof(float));

    // Split inputs/weights into bf16 hi/lo
    dim3 pxg((BT * LSEQ * DIM) / (256 * 4), 3);
    prep_x<<<pxg, 256>>>(queries, keys, values);
    dim3 pwg((DIM * DIM) / 256, 3);
    prep_w<<<pwg, 256>>>(Wq, Wk, Wv);

    // HMMA projection
    dim3 pg(12, 4, BT);
    proj_mma_kernel<<<pg, 256, SM_TOT>>>();

    // fp32 attention (unchanged)
    dim3 ag(8, NH, BT);
    attn_kernel<<<ag, 128>>>(amask, w_head, tau, delta, out);
}

// round 12
// speedup vs baseline: 2.3732x; 1.6728x over previous
#include <cuda_runtime.h>
#include <cuda_bf16.h>
#include <math.h>
#include <cstdint>

#define BT   32          // B*T
#define LSEQ 512
#define DIM  512
#define NH   8
#define ED   64
#define NTOT 1536        // packed Q|K|V width

// Packed projected tensor, split bf16: [bt][l][ Q(512) | K(512) | V(512) ]
__device__ __nv_bfloat16 g_phi[(size_t)BT * LSEQ * NTOT];
__device__ __nv_bfloat16 g_plo[(size_t)BT * LSEQ * NTOT];

// Split-bf16 GEMM operands (prepared once per launch)
__device__ __nv_bfloat16 g_xhi[(size_t)3 * BT * LSEQ * DIM];   // [sel][bt][l][k]
__device__ __nv_bfloat16 g_xlo[(size_t)3 * BT * LSEQ * DIM];
__device__ __nv_bfloat16 g_whi[(size_t)3 * DIM * DIM];         // [sel][n][k]
__device__ __nv_bfloat16 g_wlo[(size_t)3 * DIM * DIM];

// ===========================================================================
// Warp-MMA helpers (baseline PTX, safe at compute_103)
// ===========================================================================
__device__ __forceinline__ uint32_t smem_to_u32(const void* p) {
    uint32_t a;
    asm("{ .reg .u64 t; cvta.to.shared.u64 t, %1; cvt.u32.u64 %0, t; }"
        : "=r"(a) : "l"(p));
    return a;
}
__device__ __forceinline__ void ldsm_x4(uint32_t r[4], uint32_t addr) {
    asm volatile("ldmatrix.sync.aligned.m8n8.x4.shared.b16 {%0,%1,%2,%3}, [%4];"
                 : "=r"(r[0]), "=r"(r[1]), "=r"(r[2]), "=r"(r[3]) : "r"(addr));
}
__device__ __forceinline__ void ldsm_x4t(uint32_t r[4], uint32_t addr) {
    asm volatile("ldmatrix.sync.aligned.m8n8.x4.trans.shared.b16 {%0,%1,%2,%3}, [%4];"
                 : "=r"(r[0]), "=r"(r[1]), "=r"(r[2]), "=r"(r[3]) : "r"(addr));
}
__device__ __forceinline__ void mma16816(float c[4], const uint32_t a[4],
                                         const uint32_t b[2]) {
    asm volatile(
        "mma.sync.aligned.m16n8k16.row.col.f32.bf16.bf16.f32 "
        "{%0,%1,%2,%3}, {%4,%5,%6,%7}, {%8,%9}, {%0,%1,%2,%3};"
        : "+f"(c[0]), "+f"(c[1]), "+f"(c[2]), "+f"(c[3])
        : "r"(a[0]), "r"(a[1]), "r"(a[2]), "r"(a[3]), "r"(b[0]), "r"(b[1]));
}
__device__ __forceinline__ uint32_t pack_bf16(float x, float y) {
    __nv_bfloat162 t = __floats2bfloat162_rn(x, y);
    return *(uint32_t*)&t;
}

#define ROWB 144            // 72 bf16 row stride in bytes

// ===========================================================================
// Prep kernels: split fp32 -> (bf16 hi, bf16 lo)
// ===========================================================================
__global__ __launch_bounds__(256) void prep_x(
    const float* __restrict__ q, const float* __restrict__ k,
    const float* __restrict__ v)
{
    const int sel = blockIdx.y;
    const float* s = (sel == 0 ? q : (sel == 1 ? k : v));
    size_t i = ((size_t)blockIdx.x * 256 + threadIdx.x) * 4;
    float4 x = *(const float4*)&s[i];
    size_t o = (size_t)sel * BT * LSEQ * DIM + i;
    float xs[4] = {x.x, x.y, x.z, x.w};
#pragma unroll
    for (int j = 0; j < 4; j++) {
        __nv_bfloat16 h = __float2bfloat16(xs[j]);
        g_xhi[o + j] = h;
        g_xlo[o + j] = __float2bfloat16(xs[j] - __bfloat162float(h));
    }
}

__global__ __launch_bounds__(256) void prep_w(
    const float* __restrict__ wq, const float* __restrict__ wk,
    const float* __restrict__ wv)
{
    const int sel = blockIdx.y;
    const float* w = (sel == 0 ? wq : (sel == 1 ? wk : wv));
    int idx = blockIdx.x * 256 + threadIdx.x;
    int kk = idx >> 9;
    int n  = idx & 511;
    float x = w[(size_t)kk * 512 + n];
    __nv_bfloat16 h = __float2bfloat16(x);
    size_t o = (size_t)sel * DIM * DIM + (size_t)n * DIM + kk;
    g_whi[o] = h;
    g_wlo[o] = __float2bfloat16(x - __bfloat162float(h));
}

// ===========================================================================
// Projection via warp MMA: C[128x128] per block, 8 warps, 64x32 warp tiles.
// Writes split-bf16 hi/lo packed QKV.
// ===========================================================================
#define SM_AHI 0
#define SM_ALO 18432
#define SM_BHI 36864
#define SM_BLO 55296
#define SM_TOT 73728

__global__ __launch_bounds__(256, 2) void proj_mma_kernel()
{
    extern __shared__ __align__(128) char smem[];
    const uint32_t sb = smem_to_u32(smem);
    const int tid  = threadIdx.x;
    const int wid  = tid >> 5;
    const int lane = tid & 31;

    const int bt    = blockIdx.z;
    const int ntile = blockIdx.x;
    const int sel   = ntile >> 2;
    const int n0    = ntile << 7;
    const int wn0   = n0 - (sel << 9);
    const int m0    = blockIdx.y << 7;

    const __nv_bfloat16* xhi = g_xhi + ((size_t)sel * BT + bt) * LSEQ * DIM;
    const __nv_bfloat16* xlo = g_xlo + ((size_t)sel * BT + bt) * LSEQ * DIM;
    const __nv_bfloat16* whi = g_whi + (size_t)sel * DIM * DIM;
    const __nv_bfloat16* wlo = g_wlo + (size_t)sel * DIM * DIM;

    const int wm = (wid >> 2) * 64;
    const int wn = (wid & 3) * 32;

    const uint32_t a_off = (uint32_t)((lane & 15) * ROWB + (lane >> 4) * 16);
    const uint32_t b_off = (uint32_t)((((lane >> 4) & 1) * 8 + (lane & 7)) * ROWB
                                      + ((lane >> 3) & 1) * 16);

    float c[4][4][4];
#pragma unroll
    for (int mi = 0; mi < 4; mi++)
#pragma unroll
        for (int ni = 0; ni < 4; ni++)
#pragma unroll
            for (int j = 0; j < 4; j++) c[mi][ni][j] = 0.f;

    for (int ki = 0; ki < 8; ki++) {
        const int k0 = ki * 64;
        __syncthreads();
#pragma unroll
        for (int i = 0; i < 4; i++) {
            int idx = tid + i * 256;
            int row = idx >> 3;
            int c8  = idx & 7;
            uint32_t so = (uint32_t)(row * ROWB + c8 * 16);
            size_t xo = (size_t)(m0 + row) * DIM + k0 + c8 * 8;
            size_t wo = (size_t)(wn0 + row) * DIM + k0 + c8 * 8;
            *(uint4*)(smem + SM_AHI + so) = *(const uint4*)(xhi + xo);
            *(uint4*)(smem + SM_ALO + so) = *(const uint4*)(xlo + xo);
            *(uint4*)(smem + SM_BHI + so) = *(const uint4*)(whi + wo);
            *(uint4*)(smem + SM_BLO + so) = *(const uint4*)(wlo + wo);
        }
        __syncthreads();

#pragma unroll
        for (int ks = 0; ks < 4; ks++) {
            uint32_t bhi[4][2], blo[4][2];
#pragma unroll
            for (int nj = 0; nj < 2; nj++) {
                uint32_t bd = sb + (uint32_t)((wn + nj * 16) * ROWB + ks * 32) + b_off;
                uint32_t t[4];
                ldsm_x4(t, bd + SM_BHI);
                bhi[nj * 2][0] = t[0]; bhi[nj * 2][1] = t[1];
                bhi[nj * 2 + 1][0] = t[2]; bhi[nj * 2 + 1][1] = t[3];
                ldsm_x4(t, bd + SM_BLO);
                blo[nj * 2][0] = t[0]; blo[nj * 2][1] = t[1];
                blo[nj * 2 + 1][0] = t[2]; blo[nj * 2 + 1][1] = t[3];
            }
#pragma unroll
            for (int mi = 0; mi < 4; mi++) {
                uint32_t ahi[4], alo[4];
                uint32_t ad = sb + (uint32_t)((wm + mi * 16) * ROWB + ks * 32) + a_off;
                ldsm_x4(ahi, ad + SM_AHI);
                ldsm_x4(alo, ad + SM_ALO);
#pragma unroll
                for (int ni = 0; ni < 4; ni++) {
                    mma16816(c[mi][ni], ahi, bhi[ni]);
                    mma16816(c[mi][ni], ahi, blo[ni]);
                    mma16816(c[mi][ni], alo, bhi[ni]);
                }
            }
        }
    }

    // Writeout: split fp32 fragment -> (hi, lo) bf16 pairs
    const int g  = lane >> 2;
    const int tg = (lane & 3) * 2;
    const size_t cb = ((size_t)bt * LSEQ + m0) * NTOT + n0;
#pragma unroll
    for (int mi = 0; mi < 4; mi++)
#pragma unroll
        for (int ni = 0; ni < 4; ni++) {
            int r   = wm + mi * 16 + g;
            int col = wn + ni * 8 + tg;
#pragma unroll
            for (int hh = 0; hh < 2; hh++) {
                size_t off = cb + (size_t)(r + 8 * hh) * NTOT + col;
                float v0 = c[mi][ni][2 * hh], v1 = c[mi][ni][2 * hh + 1];
                __nv_bfloat16 h0 = __float2bfloat16(v0);
                __nv_bfloat16 h1 = __float2bfloat16(v1);
                __nv_bfloat162 hp; hp.x = h0; hp.y = h1;
                __nv_bfloat162 lp;
                lp.x = __float2bfloat16(v0 - __bfloat162float(h0));
                lp.y = __float2bfloat16(v1 - __bfloat162float(h1));
                *(__nv_bfloat162*)&g_phi[off] = hp;
                *(__nv_bfloat162*)&g_plo[off] = lp;
            }
        }
}

// ===========================================================================
// Attention via warp MMA, flash-style on fragments.
// Block = 128 queries x (bt, h). 8 warps x 16 query rows each.
// Chunks of 64 keys: S = QK^T (3-term split), softmax on fragments (quad
// shuffles), P split hi/lo in registers, O += PV (3-term, ldmatrix.trans V).
// ===========================================================================
#define SA_QHI 0
#define SA_QLO 18432
#define SA_KHI 36864
#define SA_KLO 46080
#define SA_VHI 55296
#define SA_VLO 64512
#define SA_MS  73728                     // float[128][68]
#define SA_TOT (SA_MS + 128 * 68 * 4)    // 108544

__global__ __launch_bounds__(256) void attn_mma_kernel(
    const float* __restrict__ mask, const float* __restrict__ w_head,
    const float* __restrict__ tau, const float* __restrict__ delta,
    float* __restrict__ out)
{
    extern __shared__ __align__(128) char smem[];
    float* Ms = (float*)(smem + SA_MS);
    const uint32_t sb = smem_to_u32(smem);
    const int tid  = threadIdx.x;
    const int wid  = tid >> 5;
    const int lane = tid & 31;
    const int g    = lane >> 2;          // fragment row octet
    const int tg   = (lane & 3) * 2;     // fragment col pair

    const int bt = blockIdx.z;
    const int h  = blockIdx.y;
    const int l0 = blockIdx.x * 128;
    const int qb = wid * 16;             // warp query-row base within tile

    const __nv_bfloat16* phi = g_phi + (size_t)bt * LSEQ * NTOT;
    const __nv_bfloat16* plo = g_plo + (size_t)bt * LSEQ * NTOT;
    const int hoff = h * ED;

    const uint32_t a_off = (uint32_t)((lane & 15) * ROWB + (lane >> 4) * 16);
    const uint32_t b_off = (uint32_t)((((lane >> 4) & 1) * 8 + (lane & 7)) * ROWB
                                      + ((lane >> 3) & 1) * 16);
    const uint32_t v_off = a_off;        // trans-V pattern == A pattern

    // ---- Stage Q tile (128 x 64, hi/lo) ----
#pragma unroll
    for (int i = 0; i < 4; i++) {
        int idx = tid + i * 256;         // 0..1023
        int row = idx >> 3;
        int c8  = idx & 7;
        uint32_t so = (uint32_t)(row * ROWB + c8 * 16);
        size_t go = (size_t)(l0 + row) * NTOT + hoff + c8 * 8;
        *(uint4*)(smem + SA_QHI + so) = *(const uint4*)(phi + go);
        *(uint4*)(smem + SA_QLO + so) = *(const uint4*)(plo + go);
    }
    __syncthreads();

    // ---- Preload Q fragments ----
    uint32_t qh[4][4], ql[4][4];
#pragma unroll
    for (int ks = 0; ks < 4; ks++) {
        uint32_t ad = sb + (uint32_t)(qb * ROWB + ks * 32) + a_off;
        ldsm_x4(qh[ks], ad + SA_QHI);
        ldsm_x4(ql[ks], ad + SA_QLO);
    }

    const float tv = tau[0] * 0.125f;
    const float dv = delta[0] * 0.125f;

    float o[8][4];
#pragma unroll
    for (int ne = 0; ne < 8; ne++)
#pragma unroll
        for (int j = 0; j < 4; j++) o[ne][j] = 0.f;
    float m0r = -1e30f, m1r = -1e30f;    // running rowmax (rows g, g+8)
    float ls0 = 0.f, ls1 = 0.f;          // per-lane partial row sums

    for (int s0 = 0; s0 < LSEQ; s0 += 64) {
        __syncthreads();
        // ---- Stage K/V chunk (64 x 64, hi/lo) ----
#pragma unroll
        for (int i = 0; i < 2; i++) {
            int idx = tid + i * 256;     // 0..511
            int row = idx >> 3;
            int c8  = idx & 7;
            uint32_t so = (uint32_t)(row * ROWB + c8 * 16);
            size_t ko = (size_t)(s0 + row) * NTOT + 512 + hoff + c8 * 8;
            size_t vo = (size_t)(s0 + row) * NTOT + 1024 + hoff + c8 * 8;
            *(uint4*)(smem + SA_KHI + so) = *(const uint4*)(phi + ko);
            *(uint4*)(smem + SA_KLO + so) = *(const uint4*)(plo + ko);
            *(uint4*)(smem + SA_VHI + so) = *(const uint4*)(phi + vo);
            *(uint4*)(smem + SA_VLO + so) = *(const uint4*)(plo + vo);
        }
        // ---- Stage mask chunk (128 x 64 fp32, stride 68) ----
#pragma unroll
        for (int i = 0; i < 8; i++) {
            int idx = tid + i * 256;     // 0..2047
            int row = idx >> 4;
            int c4  = (idx & 15) * 4;
            *(float4*)&Ms[row * 68 + c4] =
                *(const float4*)&mask[(size_t)(l0 + row) * LSEQ + s0 + c4];
        }
        __syncthreads();

        // ---- S = Q K^T (16 x 64 per warp, 3-term split) ----
        float sc[8][4];
#pragma unroll
        for (int ni = 0; ni < 8; ni++)
#pragma unroll
            for (int j = 0; j < 4; j++) sc[ni][j] = 0.f;

#pragma unroll
        for (int ks = 0; ks < 4; ks++) {
            uint32_t bhi[8][2], blo[8][2];
#pragma unroll
            for (int nj = 0; nj < 4; nj++) {
                uint32_t bd = sb + (uint32_t)(nj * 16 * ROWB + ks * 32) + b_off;
                uint32_t t[4];
                ldsm_x4(t, bd + SA_KHI);
                bhi[nj * 2][0] = t[0]; bhi[nj * 2][1] = t[1];
                bhi[nj * 2 + 1][0] = t[2]; bhi[nj * 2 + 1][1] = t[3];
                ldsm_x4(t, bd + SA_KLO);
                blo[nj * 2][0] = t[0]; blo[nj * 2][1] = t[1];
                blo[nj * 2 + 1][0] = t[2]; blo[nj * 2 + 1][1] = t[3];
            }
#pragma unroll
            for (int ni = 0; ni < 8; ni++) {
                mma16816(sc[ni], qh[ks], bhi[ni]);
                mma16816(sc[ni], qh[ks], blo[ni]);
                mma16816(sc[ni], ql[ks], bhi[ni]);
            }
        }

        // ---- epilogue: (s*tau + delta)*scale*mask; rowmax ----
        float tmax0 = -1e30f, tmax1 = -1e30f;
#pragma unroll
        for (int ni = 0; ni < 8; ni++) {
            int col = ni * 8 + tg;
            float2 mv0 = *(const float2*)&Ms[(qb + g) * 68 + col];
            float2 mv1 = *(const float2*)&Ms[(qb + g + 8) * 68 + col];
            sc[ni][0] = fmaf(sc[ni][0], tv, dv) * mv0.x;
            sc[ni][1] = fmaf(sc[ni][1], tv, dv) * mv0.y;
            sc[ni][2] = fmaf(sc[ni][2], tv, dv) * mv1.x;
            sc[ni][3] = fmaf(sc[ni][3], tv, dv) * mv1.y;
            tmax0 = fmaxf(tmax0, fmaxf(sc[ni][0], sc[ni][1]));
            tmax1 = fmaxf(tmax1, fmaxf(sc[ni][2], sc[ni][3]));
        }
        // quad reduce (lanes of same g)
        tmax0 = fmaxf(tmax0, __shfl_xor_sync(0xffffffffu, tmax0, 1));
        tmax0 = fmaxf(tmax0, __shfl_xor_sync(0xffffffffu, tmax0, 2));
        tmax1 = fmaxf(tmax1, __shfl_xor_sync(0xffffffffu, tmax1, 1));
        tmax1 = fmaxf(tmax1, __shfl_xor_sync(0xffffffffu, tmax1, 2));

        float mn0 = fmaxf(m0r, tmax0), mn1 = fmaxf(m1r, tmax1);
        float cr0 = __expf(m0r - mn0),  cr1 = __expf(m1r - mn1);
        m0r = mn0; m1r = mn1;
        ls0 *= cr0; ls1 *= cr1;
#pragma unroll
        for (int ne = 0; ne < 8; ne++) {
            o[ne][0] *= cr0; o[ne][1] *= cr0;
            o[ne][2] *= cr1; o[ne][3] *= cr1;
        }

        // ---- P = exp(S - m), split hi/lo, repack as A fragments ----
        uint32_t pah[4][4], pal[4][4];   // [kt][frag]
#pragma unroll
        for (int ni = 0; ni < 8; ni++) {
            float p0 = __expf(sc[ni][0] - mn0);
            float p1 = __expf(sc[ni][1] - mn0);
            float p2 = __expf(sc[ni][2] - mn1);
            float p3 = __expf(sc[ni][3] - mn1);
            ls0 += p0 + p1; ls1 += p2 + p3;
            float h0 = __bfloat162float(__float2bfloat16(p0));
            float h1 = __bfloat162float(__float2bfloat16(p1));
            float h2 = __bfloat162float(__float2bfloat16(p2));
            float h3 = __bfloat162float(__float2bfloat16(p3));
            int kt = ni >> 1, sl = (ni & 1) * 2;     // a0/a1 (k-lo) vs a2/a3 (k-hi)
            pah[kt][sl + 0] = pack_bf16(h0, h1);
            pah[kt][sl + 1] = pack_bf16(h2, h3);
            pal[kt][sl + 0] = pack_bf16(p0 - h0, p1 - h1);
            pal[kt][sl + 1] = pack_bf16(p2 - h2, p3 - h3);
        }
        // NOTE frag order fix: a-frag = {a0,a1,a2,a3} = {rowg klo, rowg+8 klo,
        // rowg khi, rowg+8 khi}. Above: sl+0 holds (p0,p1) = row g cols pair,
        // sl+1 holds rows g+8. For ni even (k-lo): a0 = (p0,p1), a1 = (p2,p3);
        // ni odd (k-hi): a2, a3. Mapping: pah[kt][0]=a0, [1]=a1, [2]=a2, [3]=a3. OK.

        // ---- O += P V (3-term split; V via ldmatrix.trans) ----
#pragma unroll
        for (int kt = 0; kt < 4; kt++) {
            uint32_t vh[8][2], vl[8][2];
#pragma unroll
            for (int pr = 0; pr < 4; pr++) {
                uint32_t vd = sb + (uint32_t)(kt * 16 * ROWB + pr * 32) + v_off;
                uint32_t t[4];
                ldsm_x4t(t, vd + SA_VHI);
                vh[pr * 2][0] = t[0]; vh[pr * 2][1] = t[1];
                vh[pr * 2 + 1][0] = t[2]; vh[pr * 2 + 1][1] = t[3];
                ldsm_x4t(t, vd + SA_VLO);
                vl[pr * 2][0] = t[0]; vl[pr * 2][1] = t[1];
                vl[pr * 2 + 1][0] = t[2]; vl[pr * 2 + 1][1] = t[3];
            }
#pragma unroll
            for (int ne = 0; ne < 8; ne++) {
                mma16816(o[ne], pah[kt], vh[ne]);
                mma16816(o[ne], pah[kt], vl[ne]);
                mma16816(o[ne], pal[kt], vh[ne]);
            }
        }
    }

    // ---- finalize: quad-reduce lsum, scale by w_head/lsum, atomic out ----
    ls0 += __shfl_xor_sync(0xffffffffu, ls0, 1);
    ls0 += __shfl_xor_sync(0xffffffffu, ls0, 2);
    ls1 += __shfl_xor_sync(0xffffffffu, ls1, 1);
    ls1 += __shfl_xor_sync(0xffffffffu, ls1, 2);
    const float wh = w_head[h];
    const float f0 = wh / ls0, f1 = wh / ls1;

    const int r0 = l0 + qb + g;
    float* ob = out + (size_t)bt * LSEQ * ED;
#pragma unroll
    for (int ne = 0; ne < 8; ne++) {
        int col = ne * 8 + tg;
        atomicAdd(&ob[(size_t)r0 * ED + col],       o[ne][0] * f0);
        atomicAdd(&ob[(size_t)r0 * ED + col + 1],   o[ne][1] * f0);
        atomicAdd(&ob[(size_t)(r0 + 8) * ED + col],     o[ne][2] * f1);
        atomicAdd(&ob[(size_t)(r0 + 8) * ED + col + 1], o[ne][3] * f1);
    }
}

// ---------------------------------------------------------------------------
extern "C" void kernel_launch(void* const* d_in, const int* in_sizes, int n_in,
                              void* d_out, int out_size) {
    (void)in_sizes; (void)n_in;
    const float* queries = (const float*)d_in[0];
    const float* keys    = (const float*)d_in[1];
    const float* values  = (const float*)d_in[2];
    const float* amask   = (const float*)d_in[3];
    const float* Wq      = (const float*)d_in[4];
    const float* Wk      = (const float*)d_in[5];
    const float* Wv      = (const float*)d_in[6];
    const float* w_head  = (const float*)d_in[7];
    const float* tau     = (const float*)d_in[8];
    const float* delta   = (const float*)d_in[9];
    float* out = (float*)d_out;

    cudaFuncSetAttribute(proj_mma_kernel,
                         cudaFuncAttributeMaxDynamicSharedMemorySize, SM_TOT);
    cudaFuncSetAttribute(attn_mma_kernel,
                         cudaFuncAttributeMaxDynamicSharedMemorySize, SA_TOT);

    cudaMemsetAsync(out, 0, (size_t)out_size * sizeof(float));

    dim3 pxg((BT * LSEQ * DIM) / (256 * 4), 3);
    prep_x<<<pxg, 256>>>(queries, keys, values);
    dim3 pwg((DIM * DIM) / 256, 3);
    prep_w<<<pwg, 256>>>(Wq, Wk, Wv);

    dim3 pg(12, 4, BT);
    proj_mma_kernel<<<pg, 256, SM_TOT>>>();

    dim3 ag(4, NH, BT);      // 128-query tiles x heads x bt
    attn_mma_kernel<<<ag, 256, SA_TOT>>>(amask, w_head, tau, delta, out);
}